// round 1
// baseline (speedup 1.0000x reference)
#include <cuda_runtime.h>
#include <math.h>

// Problem constants
#define Bb 4
#define Ss 8192
#define Ff 512
#define Nn 64
#define Hh 2048
#define BSr (Bb*Ss)            // 32768 rows

// ---------------- scratch (device globals; no allocations allowed) ----------
__device__ float d_h[BSr*Ff];          // 64MB: h (LN1 out), reused as h2
__device__ float d_x1[BSr*Ff];         // 64MB: first residual result
__device__ float d_g[BSr*Hh];          // 256MB: MLP hidden; first 64MB also used as y-scratch
__device__ float d_buT[256*BSr];       // 32MB: Bu (transposed), scanned in place -> xs
__device__ float d_mods[Bb*6*Ff];      // adaLN modulation
__device__ float d_wbu[256*Ff];        // B_bar combined weight  [ch][f]
__device__ float d_wout[256*Ff];       // C^T @ proj_w combined  [ch][f']
__device__ float d_wd[Ff*Ff];          // diag(D) @ proj_w combined
__device__ float2 d_abar[128];         // per complex channel (0..63 fwd, 64..127 bwd)

// ---------------- prep kernels ----------------------------------------------

// mods = silu(cond) @ ada_w + ada_b     grid(12,4) x 256
__global__ void prep_mods_k(const float* __restrict__ cond,
                            const float* __restrict__ ada_w,
                            const float* __restrict__ ada_b) {
    __shared__ float sc[Ff];
    int b = blockIdx.y;
    for (int i = threadIdx.x; i < Ff; i += 256) {
        float v = cond[b*Ff + i];
        sc[i] = v / (1.0f + expf(-v));
    }
    __syncthreads();
    int j = blockIdx.x * 256 + threadIdx.x;     // 0..3071
    float acc = ada_b[j];
    #pragma unroll 8
    for (int f = 0; f < Ff; f++) acc += sc[f] * ada_w[f*(6*Ff) + j];
    d_mods[b*(6*Ff) + j] = acc;
}

// per-direction SSM discretization -> a_bar, B_bar weight.  grid(128) x 512
__global__ void prep_ssm_k(const float* __restrict__ fla, const float* __restrict__ fai,
                           const float* __restrict__ fbr, const float* __restrict__ fbi,
                           const float* __restrict__ fld,
                           const float* __restrict__ bla, const float* __restrict__ bai,
                           const float* __restrict__ bbr, const float* __restrict__ bbi,
                           const float* __restrict__ bld) {
    int n   = blockIdx.x & 63;
    int dir = blockIdx.x >> 6;
    const float* logAre = dir ? bla : fla;
    const float* Aim    = dir ? bai : fai;
    const float* Bre    = dir ? bbr : fbr;
    const float* Bim    = dir ? bbi : fbi;
    const float* logdt  = dir ? bld : fld;

    float dt   = expf(logdt[n]);
    float Are  = -expf(logAre[n]);
    float Aimv = Aim[n];
    float er   = expf(Are * dt);
    float abr  = er * cosf(Aimv * dt);
    float abi  = er * sinf(Aimv * dt);
    // coef = (a_bar - 1) / (A + 1e-8)
    float dre = Are + 1e-8f, dim = Aimv;
    float den = dre*dre + dim*dim;
    float nre = abr - 1.0f, nim = abi;
    float cre = (nre*dre + nim*dim) / den;
    float cim = (nim*dre - nre*dim) / den;

    if (threadIdx.x == 0) d_abar[dir*64 + n] = make_float2(abr, abi);

    int f = threadIdx.x;                               // 512 threads
    float br = Bre[n*Ff + f], bi = Bim[n*Ff + f];
    d_wbu[(dir*128 + n     )*Ff + f] = cre*br - cim*bi;   // Re(B_bar)
    d_wbu[(dir*128 + 64 + n)*Ff + f] = cre*bi + cim*br;   // Im(B_bar)
}

// W_out[ch][f'] = (+/-) sum_f C[f][n] * proj_w[poff+f][f']   grid(256) x 512
__global__ void prep_wout_k(const float* __restrict__ fcr, const float* __restrict__ fci,
                            const float* __restrict__ bcr, const float* __restrict__ bci,
                            const float* __restrict__ proj_w) {
    int ch  = blockIdx.x;
    int blk = ch >> 6, n = ch & 63;
    const float* C = (blk == 0) ? fcr : (blk == 1) ? fci : (blk == 2) ? bcr : bci;
    float sign = (blk == 1 || blk == 3) ? -1.0f : 1.0f;
    int poff = (blk >= 2) ? Ff : 0;

    __shared__ float sC[Ff];
    for (int i = threadIdx.x; i < Ff; i += 512) sC[i] = C[i*Nn + n];
    __syncthreads();
    int fp = threadIdx.x;
    float acc = 0.0f;
    #pragma unroll 8
    for (int f = 0; f < Ff; f++) acc += sC[f] * proj_w[(poff + f)*Ff + fp];
    d_wout[ch*Ff + fp] = sign * acc;
}

// W_D = diag(D_fwd)@P[0:F] + diag(D_bwd)@P[F:2F]   grid(1024) x 256
__global__ void prep_wd_k(const float* __restrict__ Df, const float* __restrict__ Db,
                          const float* __restrict__ proj_w) {
    int idx = blockIdx.x * 256 + threadIdx.x;   // 0..262143
    int f = idx >> 9;
    d_wd[idx] = Df[f]*proj_w[idx] + Db[f]*proj_w[idx + Ff*Ff];
}

// ---------------- LN + adaLN modulation -------------------------------------
// out = LN(in)*(1+sc)+sh ; moff selects {sh1,sc1} or {sh2,sc2}. grid(32768) x 128
__global__ void ln_mod_k(const float* __restrict__ in, float* __restrict__ out, int moff) {
    int row = blockIdx.x;
    int bb  = row >> 13;
    int tid = threadIdx.x;
    float4 v = ((const float4*)(in + (size_t)row*Ff))[tid];
    float s  = v.x+v.y+v.z+v.w;
    float sq = v.x*v.x + v.y*v.y + v.z*v.z + v.w*v.w;
    #pragma unroll
    for (int o = 16; o > 0; o >>= 1) {
        s  += __shfl_down_sync(0xffffffffu, s,  o);
        sq += __shfl_down_sync(0xffffffffu, sq, o);
    }
    __shared__ float ss[4], ssq[4];
    int w = tid >> 5, l = tid & 31;
    if (l == 0) { ss[w] = s; ssq[w] = sq; }
    __syncthreads();
    if (tid == 0) { ss[0]  = ss[0]+ss[1]+ss[2]+ss[3];
                    ssq[0] = ssq[0]+ssq[1]+ssq[2]+ssq[3]; }
    __syncthreads();
    float mu  = ss[0]  * (1.0f/512.0f);
    float var = ssq[0] * (1.0f/512.0f) - mu*mu;
    float rstd = rsqrtf(var + 1e-5f);
    const float* md = d_mods + bb*(6*Ff) + moff;
    int f = tid*4;
    float4 o4;
    o4.x = (v.x-mu)*rstd*(1.0f+md[Ff+f+0]) + md[f+0];
    o4.y = (v.y-mu)*rstd*(1.0f+md[Ff+f+1]) + md[f+1];
    o4.z = (v.z-mu)*rstd*(1.0f+md[Ff+f+2]) + md[f+2];
    o4.w = (v.w-mu)*rstd*(1.0f+md[Ff+f+3]) + md[f+3];
    ((float4*)(out + (size_t)row*Ff))[tid] = o4;
}

// ---------------- generic tiled fp32 GEMM ------------------------------------
// C[M,N] = A @ B   (TA: 0 = A[m][k] lda=K ; 1 = A stored as AT[k][m], lda = m-stride)
//                  (TB: 0 = B[k][n] ldb=N ; 1 = B stored as BT[n][k], ldb = k-count)
#define BM 128
#define BN 128
#define BK 16

template<int TA, int TB, int EPI>
__global__ __launch_bounds__(256, 2) void gemm_k(
    const float* __restrict__ A, const float* __restrict__ Bm, float* __restrict__ C,
    int M, int N, int K, int lda, int ldb, int ldc,
    const float* __restrict__ aux1, const float* __restrict__ aux2,
    const float* __restrict__ aux3) {
    __shared__ float As[BK][BM + 4];
    __shared__ float Bs[BK][BN + 4];
    int tid = threadIdx.x;
    int tx = tid & 15, ty = tid >> 4;
    int m0 = blockIdx.y * BM, n0 = blockIdx.x * BN;
    float acc[8][8] = {};

    for (int k0 = 0; k0 < K; k0 += BK) {
        // --- load A tile ---
        if (TA == 0) {
            #pragma unroll
            for (int i = 0; i < 2; i++) {
                int idx4 = tid*2 + i;
                int m = idx4 >> 2, kq = idx4 & 3;
                float4 v = *(const float4*)(A + (size_t)(m0+m)*lda + k0 + kq*4);
                As[kq*4+0][m] = v.x; As[kq*4+1][m] = v.y;
                As[kq*4+2][m] = v.z; As[kq*4+3][m] = v.w;
            }
        } else {
            #pragma unroll
            for (int i = 0; i < 2; i++) {
                int idx4 = tid*2 + i;
                int k = idx4 >> 5, mq = idx4 & 31;
                float4 v = *(const float4*)(A + (size_t)(k0+k)*lda + m0 + mq*4);
                *(float4*)&As[k][mq*4] = v;
            }
        }
        // --- load B tile ---
        if (TB == 0) {
            #pragma unroll
            for (int i = 0; i < 2; i++) {
                int idx4 = tid*2 + i;
                int k = idx4 >> 5, nq = idx4 & 31;
                float4 v = *(const float4*)(Bm + (size_t)(k0+k)*ldb + n0 + nq*4);
                *(float4*)&Bs[k][nq*4] = v;
            }
        } else {
            #pragma unroll
            for (int i = 0; i < 2; i++) {
                int idx4 = tid*2 + i;
                int n = idx4 >> 2, kq = idx4 & 3;
                float4 v = *(const float4*)(Bm + (size_t)(n0+n)*ldb + k0 + kq*4);
                Bs[kq*4+0][n] = v.x; Bs[kq*4+1][n] = v.y;
                Bs[kq*4+2][n] = v.z; Bs[kq*4+3][n] = v.w;
            }
        }
        __syncthreads();
        #pragma unroll
        for (int k = 0; k < BK; k++) {
            float a[8], b[8];
            #pragma unroll
            for (int i = 0; i < 8; i++) a[i] = As[k][ty*8 + i];
            #pragma unroll
            for (int j = 0; j < 8; j++) b[j] = Bs[k][tx*8 + j];
            #pragma unroll
            for (int i = 0; i < 8; i++)
                #pragma unroll
                for (int j = 0; j < 8; j++)
                    acc[i][j] = fmaf(a[i], b[j], acc[i][j]);
        }
        __syncthreads();
    }

    // --- epilogue ---
    #pragma unroll
    for (int i = 0; i < 8; i++) {
        int m = m0 + ty*8 + i;
        #pragma unroll
        for (int j = 0; j < 8; j++) {
            int n = n0 + tx*8 + j;
            float v = acc[i][j];
            size_t off = (size_t)m * ldc + n;
            if (EPI == 0) {
                C[off] = v;
            } else if (EPI == 1) {        // x1 = x + g1*(xs_part + h_part + proj_b)
                int bb = m >> 13;
                float y = v + aux1[(size_t)m*Ff + n] + aux2[n];
                float g1 = d_mods[bb*(6*Ff) + 2*Ff + n];
                C[off] = aux3[(size_t)m*Ff + n] + g1 * y;
            } else if (EPI == 2) {        // gelu(tanh approx)(v + b1)
                float x = v + aux1[n];
                float t = tanhf(0.7978845608028654f * (x + 0.044715f * x*x*x));
                C[off] = 0.5f * x * (1.0f + t);
            } else {                      // out = x1 + g2*(v + b2)
                int bb = m >> 13;
                float g2 = d_mods[bb*(6*Ff) + 5*Ff + n];
                C[off] = aux1[off] + g2 * (v + aux2[n]);
            }
        }
    }
}

// ---------------- chunked complex scan (constant multiplier) -----------------
// grid(512) = b*128 + c ; 256 threads, 32 elems/thread, in place on d_buT.
__global__ __launch_bounds__(256) void scan_k(float* __restrict__ buT) {
    int c = blockIdx.x & 127;
    int b = blockIdx.x >> 7;
    int re_ch = (c < 64) ? c : (64 + c);
    float* pre = buT + (size_t)re_ch * BSr + b * Ss;
    float* pim = pre + (size_t)64 * BSr;
    float2 a = d_abar[c];
    bool rev = (c >= 64);
    int t = threadIdx.x, lane = t & 31, wid = t >> 5;
    int base = t * 32;

    float lre[32], lim[32];
    float xr = 0.0f, xi = 0.0f;
    #pragma unroll
    for (int j = 0; j < 32; j++) {
        int p = base + j;
        int s = rev ? (Ss - 1 - p) : p;
        float br = pre[s], bi = pim[s];
        float nr = fmaf(a.x, xr, fmaf(-a.y, xi, br));
        float ni = fmaf(a.x, xi, fmaf( a.y, xr, bi));
        xr = nr; xi = ni;
        lre[j] = xr; lim[j] = xi;
    }
    // a^32
    float2 a32 = a;
    #pragma unroll
    for (int i = 0; i < 5; i++) {
        float tr = a32.x*a32.x - a32.y*a32.y;
        a32.y = 2.0f*a32.x*a32.y; a32.x = tr;
    }
    // warp pair-scan: (A,E) with op (a1,b1)∘(a2,b2) = (a1a2, a2 b1 + b2)
    float2 pA = a32, pE = make_float2(xr, xi);
    const unsigned full = 0xffffffffu;
    #pragma unroll
    for (int d = 1; d < 32; d <<= 1) {
        float uAx = __shfl_up_sync(full, pA.x, d);
        float uAy = __shfl_up_sync(full, pA.y, d);
        float uEx = __shfl_up_sync(full, pE.x, d);
        float uEy = __shfl_up_sync(full, pE.y, d);
        if (lane >= d) {
            float ex = pA.x*uEx - pA.y*uEy + pE.x;
            float ey = pA.x*uEy + pA.y*uEx + pE.y;
            float ax = pA.x*uAx - pA.y*uAy;
            float ay = pA.x*uAy + pA.y*uAx;
            pE = make_float2(ex, ey); pA = make_float2(ax, ay);
        }
    }
    __shared__ float2 sE[8], sA[8], wpre[8];
    if (lane == 31) { sE[wid] = pE; sA[wid] = pA; }
    // exclusive within warp
    float2 exA, exE;
    exA.x = __shfl_up_sync(full, pA.x, 1);
    exA.y = __shfl_up_sync(full, pA.y, 1);
    exE.x = __shfl_up_sync(full, pE.x, 1);
    exE.y = __shfl_up_sync(full, pE.y, 1);
    if (lane == 0) { exA = make_float2(1.0f, 0.0f); exE = make_float2(0.0f, 0.0f); }
    __syncthreads();
    if (t == 0) {
        float2 P = make_float2(0.0f, 0.0f);
        #pragma unroll
        for (int w = 0; w < 8; w++) {
            wpre[w] = P;
            float px = sA[w].x*P.x - sA[w].y*P.y + sE[w].x;
            float py = sA[w].x*P.y + sA[w].y*P.x + sE[w].y;
            P = make_float2(px, py);
        }
    }
    __syncthreads();
    float2 P = wpre[wid];
    float cx = exA.x*P.x - exA.y*P.y + exE.x;
    float cy = exA.x*P.y + exA.y*P.x + exE.y;
    // apply: x_j = a^{j+1}*carry + local_j
    float2 p = a;
    #pragma unroll
    for (int j = 0; j < 32; j++) {
        float outr = p.x*cx - p.y*cy + lre[j];
        float outi = p.x*cy + p.y*cx + lim[j];
        int pp = base + j;
        int s = rev ? (Ss - 1 - pp) : pp;
        pre[s] = outr; pim[s] = outi;
        float tr = p.x*a.x - p.y*a.y;
        p.y = p.x*a.y + p.y*a.x; p.x = tr;
    }
}

// ---------------- launcher ---------------------------------------------------
extern "C" void kernel_launch(void* const* d_in, const int* in_sizes, int n_in,
                              void* d_out, int out_size) {
    const float* x       = (const float*)d_in[0];
    const float* cond    = (const float*)d_in[1];
    const float* f_la    = (const float*)d_in[2];
    const float* f_ai    = (const float*)d_in[3];
    const float* f_br    = (const float*)d_in[4];
    const float* f_bi    = (const float*)d_in[5];
    const float* f_cr    = (const float*)d_in[6];
    const float* f_ci    = (const float*)d_in[7];
    const float* f_d     = (const float*)d_in[8];
    const float* f_ld    = (const float*)d_in[9];
    const float* b_la    = (const float*)d_in[10];
    const float* b_ai    = (const float*)d_in[11];
    const float* b_br    = (const float*)d_in[12];
    const float* b_bi    = (const float*)d_in[13];
    const float* b_cr    = (const float*)d_in[14];
    const float* b_ci    = (const float*)d_in[15];
    const float* b_d     = (const float*)d_in[16];
    const float* b_ld    = (const float*)d_in[17];
    const float* proj_w  = (const float*)d_in[18];
    const float* proj_b  = (const float*)d_in[19];
    const float* ada_w   = (const float*)d_in[20];
    const float* ada_b   = (const float*)d_in[21];
    const float* mlp_w1  = (const float*)d_in[22];
    const float* mlp_b1  = (const float*)d_in[23];
    const float* mlp_w2  = (const float*)d_in[24];
    const float* mlp_b2  = (const float*)d_in[25];
    float* out = (float*)d_out;

    float *h, *x1, *g, *buT;
    cudaGetSymbolAddress((void**)&h,   d_h);
    cudaGetSymbolAddress((void**)&x1,  d_x1);
    cudaGetSymbolAddress((void**)&g,   d_g);
    cudaGetSymbolAddress((void**)&buT, d_buT);
    float* yscratch = g;   // first 64MB of d_g reused before MLP1

    // prep
    prep_mods_k<<<dim3(12, 4), 256>>>(cond, ada_w, ada_b);
    prep_ssm_k<<<128, 512>>>(f_la, f_ai, f_br, f_bi, f_ld,
                             b_la, b_ai, b_br, b_bi, b_ld);
    prep_wout_k<<<256, 512>>>(f_cr, f_ci, b_cr, b_ci, proj_w);
    prep_wd_k<<<1024, 256>>>(f_d, b_d, proj_w);

    float *wbu, *wout, *wd;
    cudaGetSymbolAddress((void**)&wbu,  d_wbu);
    cudaGetSymbolAddress((void**)&wout, d_wout);
    cudaGetSymbolAddress((void**)&wd,   d_wd);

    // h = LN(x)*(1+sc1)+sh1
    ln_mod_k<<<BSr, 128>>>(x, h, 0);

    // BuT[256][32768] = Wbu @ h^T
    gemm_k<0, 1, 0><<<dim3(BSr/BN, 256/BM), 256>>>(
        wbu, h, buT, 256, BSr, Ff, Ff, Ff, BSr, nullptr, nullptr, nullptr);

    // scan in place
    scan_k<<<512, 256>>>(buT);

    // y-part1 = xs @ Wout  (A = buT transposed)
    gemm_k<1, 0, 0><<<dim3(Ff/BN, BSr/BM), 256>>>(
        buT, wout, yscratch, BSr, Ff, 256, BSr, Ff, Ff, nullptr, nullptr, nullptr);

    // x1 = x + g1*(h @ Wd + y-part1 + proj_b)
    gemm_k<0, 0, 1><<<dim3(Ff/BN, BSr/BM), 256>>>(
        h, wd, x1, BSr, Ff, Ff, Ff, Ff, Ff, yscratch, proj_b, x);

    // h2 = LN(x1)*(1+sc2)+sh2   (reuse d_h)
    ln_mod_k<<<BSr, 128>>>(x1, h, 3*Ff);

    // g = gelu(h2 @ mlp_w1 + b1)
    gemm_k<0, 0, 2><<<dim3(Hh/BN, BSr/BM), 256>>>(
        h, mlp_w1, g, BSr, Hh, Ff, Ff, Hh, Hh, mlp_b1, nullptr, nullptr);

    // out = x1 + g2*(g @ mlp_w2 + b2)
    gemm_k<0, 0, 3><<<dim3(Ff/BN, BSr/BM), 256>>>(
        g, mlp_w2, out, BSr, Ff, Hh, Hh, Ff, Ff, x1, mlp_b2, nullptr);
}